// round 5
// baseline (speedup 1.0000x reference)
#include <cuda_runtime.h>
#include <cuda_bf16.h>
#include <cstdint>

// Problem constants
#define NUM_CHIPS 4
#define SEQ 1024
#define HIDDEN 2048
#define TOP_K 4
#define N_EXPERTS 32
#define MAX_TOK 1024
#define META_LEN 8
#define N_PER_CHIP (SEQ * TOP_K)           // 4096 assignments per chip
#define N_TOTAL (NUM_CHIPS * N_PER_CHIP)   // 16384 assignments
#define N_CHUNKS (N_TOTAL / 32)            // 512 warp-chunks (chip-major order)
#define CHUNKS_PER_WARP (N_CHUNKS / 32)    // 16
#define TOTAL_SLOTS (N_EXPERTS * MAX_TOK)  // 32768
#define BUF_ELEMS ((size_t)TOTAL_SLOTS * HIDDEN)      // 67108864
#define META_OFF  BUF_ELEMS
#define CNT_OFF   (BUF_ELEMS + (size_t)TOTAL_SLOTS * META_LEN)

// Scratch (no allocations allowed)
__device__ int g_src[TOTAL_SLOTS];   // slot -> assignment id (only first cnt_e per expert valid)
__device__ int g_cnt[N_EXPERTS];     // total per-expert count

// ---------------------------------------------------------------------------
// Fused planning kernel: ONE block, 1024 threads (32 warps).
//  Phase 1: warp w ranks+counts its 16 chunks via __match_any_sync; the
//           (expert, rank) pair for each assignment stays in registers.
//  Phase 2: warp e scans expert e's 512 chunk counts in SMEM (two-level,
//           one shuffle-scan); offsets written in place; counters emitted.
//  Phase 3: warps replay their register-held pairs -> g_src inverse map.
// ---------------------------------------------------------------------------
__global__ void __launch_bounds__(1024) plan_kernel(const int* __restrict__ idx,
                                                    float* __restrict__ out) {
    __shared__ unsigned short s_wc[N_EXPERTS][N_CHUNKS];   // counts -> offsets (32 KB)

    const int warp = threadIdx.x >> 5;
    const int lane = threadIdx.x & 31;
    const unsigned lt = (1u << lane) - 1u;

    // zero the count table (1024 threads x 16)
#pragma unroll
    for (int j = 0; j < 16; j++)
        reinterpret_cast<unsigned short*>(s_wc)[j * 1024 + threadIdx.x] = 0;
    __syncthreads();

    // Phase 1: warp w owns chunks [warp*16, warp*16+16)
    int packed[CHUNKS_PER_WARP];   // expert | rank<<8
#pragma unroll
    for (int j = 0; j < CHUNKS_PER_WARP; j++) {
        const int ch = warp * CHUNKS_PER_WARP + j;
        const int v  = idx[ch * 32 + lane];
        const unsigned m = __match_any_sync(0xFFFFFFFFu, v);
        packed[j] = v | (__popc(m & lt) << 8);
        if ((m & lt) == 0)
            s_wc[v][ch] = (unsigned short)__popc(m);
    }
    __syncthreads();

    // Phase 2: warp e scans expert e's 512 counts; lane owns 16 contiguous chunks.
    {
        const int e = warp;
        unsigned short c[16];
        int lsum = 0;
#pragma unroll
        for (int j = 0; j < 16; j++) {
            c[j] = s_wc[e][lane * 16 + j];
            lsum += c[j];
        }
        int s = lsum;
#pragma unroll
        for (int d = 1; d < 32; d <<= 1) {
            int t = __shfl_up_sync(0xFFFFFFFFu, s, d);
            if (lane >= d) s += t;
        }
        int run = s - lsum;                              // exclusive prefix of lane sums
        const int total = __shfl_sync(0xFFFFFFFFu, s, 31);
#pragma unroll
        for (int j = 0; j < 16; j++) {
            s_wc[e][lane * 16 + j] = (unsigned short)run; // overwrite with offset
            run += c[j];
        }
        if (lane == 0) {
            g_cnt[e] = total;
            out[CNT_OFF + e] = (float)total;
        }
    }
    __syncthreads();

    // Phase 3: replay -> inverse map.
#pragma unroll
    for (int j = 0; j < CHUNKS_PER_WARP; j++) {
        const int ch = warp * CHUNKS_PER_WARP + j;
        const int e  = packed[j] & 0xFF;
        const int rk = packed[j] >> 8;
        const int slot = e * MAX_TOK + (int)s_wc[e][ch] + rk;
        g_src[slot] = ch * 32 + lane;
    }
}

// ---------------------------------------------------------------------------
// Gather: one block per slot; copy token row (or zeros) + 8 meta words.
// Plain stores (round-2 config: measured 53.9us @ 65.9% DRAM).
// ---------------------------------------------------------------------------
__global__ void __launch_bounds__(256) gather_kernel(const float* __restrict__ x,
                                                     const float* __restrict__ w,
                                                     const int* __restrict__ indices,
                                                     float* __restrict__ out) {
    const int slot = blockIdx.x;
    const int e    = slot >> 10;
    const int si   = slot & (MAX_TOK - 1);
    const int t    = threadIdx.x;
    float4* dst = reinterpret_cast<float4*>(out + (size_t)slot * HIDDEN);
    float4* md  = reinterpret_cast<float4*>(out + META_OFF + (size_t)slot * META_LEN);

    if (si < g_cnt[e]) {
        const int a   = g_src[slot];
        const int c   = a >> 12;
        const int n   = a & (N_PER_CHIP - 1);
        const int tok = n >> 2;
        const float4* src =
            reinterpret_cast<const float4*>(x + ((size_t)c * SEQ + tok) * HIDDEN);
        float4 v0 = src[t];
        float4 v1 = src[t + 256];
        dst[t]       = v0;
        dst[t + 256] = v1;
        if (t == 0) {
            __nv_bfloat16 hb = __float2bfloat16(w[a]);
            unsigned short bits = __bfloat16_as_ushort(hb);
            md[0] = make_float4((float)c, (float)tok, (float)(n & 3), (float)e);
            md[1] = make_float4((float)bits, 0.f, 0.f, 0.f);
        }
    } else {
        const float4 z = make_float4(0.f, 0.f, 0.f, 0.f);
        dst[t]       = z;
        dst[t + 256] = z;
        if (t == 0) {
            const float4 neg = make_float4(-1.f, -1.f, -1.f, -1.f);
            md[0] = neg;
            md[1] = neg;
        }
    }
}

// ---------------------------------------------------------------------------
extern "C" void kernel_launch(void* const* d_in, const int* in_sizes, int n_in,
                              void* d_out, int out_size) {
    const float* x   = (const float*)d_in[0];   // [4,1024,2048] f32
    const float* wts = (const float*)d_in[1];   // [4,1024,4]    f32
    const int*   ind = (const int*)  d_in[2];   // [4,1024,4]    i32
    float* out = (float*)d_out;

    plan_kernel<<<1, 1024>>>(ind, out);
    gather_kernel<<<TOTAL_SLOTS, 256>>>(x, wts, ind, out);
}

// round 6
// speedup vs baseline: 1.1003x; 1.1003x over previous
#include <cuda_runtime.h>
#include <cuda_bf16.h>
#include <cstdint>

// Problem constants
#define NUM_CHIPS 4
#define SEQ 1024
#define HIDDEN 2048
#define TOP_K 4
#define N_EXPERTS 32
#define MAX_TOK 1024
#define META_LEN 8
#define N_PER_CHIP (SEQ * TOP_K)           // 4096 assignments per chip
#define N_TOTAL (NUM_CHIPS * N_PER_CHIP)   // 16384 assignments
#define N_CHUNKS (N_TOTAL / 32)            // 512 warp-chunks (chip-major order)
#define TOTAL_SLOTS (N_EXPERTS * MAX_TOK)  // 32768
#define BUF_ELEMS ((size_t)TOTAL_SLOTS * HIDDEN)      // 67108864
#define META_OFF  BUF_ELEMS
#define CNT_OFF   (BUF_ELEMS + (size_t)TOTAL_SLOTS * META_LEN)

#define PLAN_BLOCKS 16

// Scratch (no allocations allowed)
__device__ int g_src[TOTAL_SLOTS];               // slot -> assignment id (first cnt_e valid)
__device__ int g_cnt[N_EXPERTS];                 // per-expert totals
__device__ int g_wcount[N_EXPERTS][N_CHUNKS];    // chunk counts -> (in place) chunk offsets
__device__ unsigned g_bar;                       // monotone barrier ticket counter (never reset)

// Monotone-ticket grid barrier for a PLAN_BLOCKS-block grid (all co-resident).
// Counter only ever increases; each barrier consumes a window of PLAN_BLOCKS
// tickets, so it is CUDA-graph-replay safe with no reset kernel.
__device__ __forceinline__ void grid_bar() {
    __shared__ unsigned target;
    __syncthreads();
    __threadfence();
    if (threadIdx.x == 0) {
        unsigned t = atomicAdd(&g_bar, 1u);
        target = (t | (PLAN_BLOCKS - 1u)) + 1u;
    }
    __syncthreads();
    if (threadIdx.x == 0) {
        while (atomicAdd(&g_bar, 0u) < target) { }
    }
    __syncthreads();
    __threadfence();
}

// ---------------------------------------------------------------------------
// Planning: 16 blocks x 1024 threads. Ranks live in registers across phases.
// ---------------------------------------------------------------------------
__global__ void __launch_bounds__(1024) plan_kernel(const int* __restrict__ idx,
                                                    float* __restrict__ out) {
    const int warp  = threadIdx.x >> 5;
    const int lane  = threadIdx.x & 31;
    const int chunk = blockIdx.x * 32 + warp;      // 0..511, chip-major
    const int a     = chunk * 32 + lane;           // assignment id

    // Phase 1: per-chunk expert counts + stable within-chunk rank.
    g_wcount[lane][chunk] = 0;                     // zero this chunk's 32-expert column
    __syncwarp();
    const int e = idx[a];
    const unsigned m  = __match_any_sync(0xFFFFFFFFu, e);
    const int rk = __popc(m & ((1u << lane) - 1u));
    if (rk == 0)                                   // lowest lane of this expert group
        g_wcount[e][chunk] = __popc(m);

    grid_bar();

    // Phase 2: block 0, warp e scans expert e's 512 chunk counts (in L2),
    // two-level: lane owns 16 contiguous chunks; offsets written in place.
    if (blockIdx.x == 0) {
        const int ex = warp;
        int4 c0, c1, c2, c3;
        const int4* wc = reinterpret_cast<const int4*>(&g_wcount[ex][lane * 16]);
        c0 = wc[0]; c1 = wc[1]; c2 = wc[2]; c3 = wc[3];
        int cnt[16] = {c0.x,c0.y,c0.z,c0.w, c1.x,c1.y,c1.z,c1.w,
                       c2.x,c2.y,c2.z,c2.w, c3.x,c3.y,c3.z,c3.w};
        int lsum = 0;
#pragma unroll
        for (int j = 0; j < 16; j++) lsum += cnt[j];
        int s = lsum;
#pragma unroll
        for (int d = 1; d < 32; d <<= 1) {
            int t = __shfl_up_sync(0xFFFFFFFFu, s, d);
            if (lane >= d) s += t;
        }
        int run = s - lsum;
        const int total = __shfl_sync(0xFFFFFFFFu, s, 31);
        int4 o0 = make_int4(run,            run+cnt[0],       run+cnt[0]+cnt[1], run+cnt[0]+cnt[1]+cnt[2]);
        int off = run;
        int outv[16];
#pragma unroll
        for (int j = 0; j < 16; j++) { outv[j] = off; off += cnt[j]; }
        int4* wo = reinterpret_cast<int4*>(&g_wcount[ex][lane * 16]);
        wo[0] = make_int4(outv[0],  outv[1],  outv[2],  outv[3]);
        wo[1] = make_int4(outv[4],  outv[5],  outv[6],  outv[7]);
        wo[2] = make_int4(outv[8],  outv[9],  outv[10], outv[11]);
        wo[3] = make_int4(outv[12], outv[13], outv[14], outv[15]);
        (void)o0;
        if (lane == 0) {
            g_cnt[ex] = total;
            out[CNT_OFF + ex] = (float)total;
        }
    }

    grid_bar();

    // Phase 3: replay register-held (expert, rank) -> inverse map.
    const int slot = e * MAX_TOK + g_wcount[e][chunk] + rk;
    g_src[slot] = a;
}

// ---------------------------------------------------------------------------
// Gather: one block per slot; copy token row (or zeros) + 8 meta words.
// Plain stores (proven config: ~53us @ ~66-68% DRAM).
// ---------------------------------------------------------------------------
__global__ void __launch_bounds__(256) gather_kernel(const float* __restrict__ x,
                                                     const float* __restrict__ w,
                                                     const int* __restrict__ indices,
                                                     float* __restrict__ out) {
    const int slot = blockIdx.x;
    const int e    = slot >> 10;
    const int si   = slot & (MAX_TOK - 1);
    const int t    = threadIdx.x;
    float4* dst = reinterpret_cast<float4*>(out + (size_t)slot * HIDDEN);
    float4* md  = reinterpret_cast<float4*>(out + META_OFF + (size_t)slot * META_LEN);

    if (si < g_cnt[e]) {
        const int a   = g_src[slot];
        const int c   = a >> 12;
        const int n   = a & (N_PER_CHIP - 1);
        const int tok = n >> 2;
        const float4* src =
            reinterpret_cast<const float4*>(x + ((size_t)c * SEQ + tok) * HIDDEN);
        float4 v0 = src[t];
        float4 v1 = src[t + 256];
        dst[t]       = v0;
        dst[t + 256] = v1;
        if (t == 0) {
            __nv_bfloat16 hb = __float2bfloat16(w[a]);
            unsigned short bits = __bfloat16_as_ushort(hb);
            md[0] = make_float4((float)c, (float)tok, (float)(n & 3), (float)e);
            md[1] = make_float4((float)bits, 0.f, 0.f, 0.f);
        }
    } else {
        const float4 z = make_float4(0.f, 0.f, 0.f, 0.f);
        dst[t]       = z;
        dst[t + 256] = z;
        if (t == 0) {
            const float4 neg = make_float4(-1.f, -1.f, -1.f, -1.f);
            md[0] = neg;
            md[1] = neg;
        }
    }
}

// ---------------------------------------------------------------------------
extern "C" void kernel_launch(void* const* d_in, const int* in_sizes, int n_in,
                              void* d_out, int out_size) {
    const float* x   = (const float*)d_in[0];   // [4,1024,2048] f32
    const float* wts = (const float*)d_in[1];   // [4,1024,4]    f32
    const int*   ind = (const int*)  d_in[2];   // [4,1024,4]    i32
    float* out = (float*)d_out;

    plan_kernel<<<PLAN_BLOCKS, 1024>>>(ind, out);
    gather_kernel<<<TOTAL_SLOTS, 256>>>(x, wts, ind, out);
}